// round 8
// baseline (speedup 1.0000x reference)
#include <cuda_runtime.h>
#include <cuda_bf16.h>
#include <cstdint>

// SoftPixelRadiusCNN:
//   d      = sqrt(distsq + EPS)
//   w_i(k) = exp(-scaler * (d_k - i/ls)^2),  scaler = 10*ls*SUBDIV
//   out[v, i*F + f] = sum_k w_i(k) * features[nidx[v,k], f] / (sum_k w_i(k) + EPS)
// V=100000, K=32, F=64, SUBDIV=3.
//
// One warp per vertex; half-warps cover a full 64-col feature row (16 x float4)
// and process 2 neighbors per iteration. Neighbor {idx,w0,w1,w2} is staged in
// shared memory as one float4 -> a single broadcast LDS.128 per iteration
// replaces 4 SHFLs, and denominators accumulate in-loop (FADD) instead of a
// 45-SHFL butterfly. Targets the 78.8% L1TEX/MIO binder from the R5 profile.

#define K_NEIGH 32
#define F_DIM   64
#define SUBDIV  3
#define EPSV    1e-6f
#define OUT_F   (SUBDIV * F_DIM)
#define FULLM   0xFFFFFFFFu
#define WARPS_PER_BLOCK 8

__global__ __launch_bounds__(256)
void softpixel_kernel(const float* __restrict__ features,
                      const float* __restrict__ distsq,
                      const int*   __restrict__ nidx,
                      const float* __restrict__ ls_ptr,
                      float*       __restrict__ out,
                      int V)
{
    __shared__ float4 stage[WARPS_PER_BLOCK][K_NEIGH];

    const int lane   = threadIdx.x & 31;
    const int half   = lane >> 4;      // 0 or 1
    const int t      = lane & 15;      // float4 column group within the half
    const int wib    = threadIdx.x >> 5;            // warp in block
    const int warp0  = (blockIdx.x * blockDim.x + threadIdx.x) >> 5;
    const int nwarps = (gridDim.x * blockDim.x) >> 5;

    const float ls     = __ldg(ls_ptr);
    const float scaler = 10.0f * ls * (float)SUBDIV;
    const float inv_ls = 1.0f / ls;

    float4* const mystage = stage[wib];

    for (int v = warp0; v < V; v += nwarps) {
        // --- per-lane neighbor (k = lane): distance, index, 3 bin weights ---
        const float dsq    = __ldg(distsq + (size_t)v * K_NEIGH + lane);
        const int   my_idx = __ldg(nidx   + (size_t)v * K_NEIGH + lane);
        const float d  = sqrtf(dsq + EPSV);
        const float t1 = d - inv_ls;
        const float t2 = d - 2.0f * inv_ls;
        const float w0 = __expf(-scaler * d  * d);
        const float w1 = __expf(-scaler * t1 * t1);
        const float w2 = __expf(-scaler * t2 * t2);

        // --- stage {idx, w0, w1, w2} : one STS.128 per lane ---
        __syncwarp();   // previous vertex's stage reads complete in all lanes
        mystage[lane] = make_float4(__int_as_float(my_idx), w0, w1, w2);
        __syncwarp();   // stage visible to whole warp

        // --- gather loop: 2 neighbors/iteration (one per half-warp).
        //     One broadcast LDS.128 delivers idx + 3 weights; denominators
        //     accumulate in-loop on the FMA pipe. ---
        float4 a0 = make_float4(0.f, 0.f, 0.f, 0.f);
        float4 a1 = make_float4(0.f, 0.f, 0.f, 0.f);
        float4 a2 = make_float4(0.f, 0.f, 0.f, 0.f);
        float s0 = 0.f, s1 = 0.f, s2 = 0.f;        // this half's partial sums
        const float* fbase = features + (size_t)4 * t;

        int kj = half;                     // this half's neighbors: half, half+2, ...
        #pragma unroll
        for (int j = 0; j < K_NEIGH / 2; ++j, kj += 2) {
            const float4 p = mystage[kj];  // broadcast within each half
            const int   ik = __float_as_int(p.x);
            const float b0 = p.y, b1 = p.z, b2 = p.w;
            const float4 f = *reinterpret_cast<const float4*>(fbase + (size_t)ik * F_DIM);
            s0 += b0; s1 += b1; s2 += b2;
            a0.x = fmaf(b0, f.x, a0.x); a0.y = fmaf(b0, f.y, a0.y);
            a0.z = fmaf(b0, f.z, a0.z); a0.w = fmaf(b0, f.w, a0.w);
            a1.x = fmaf(b1, f.x, a1.x); a1.y = fmaf(b1, f.y, a1.y);
            a1.z = fmaf(b1, f.z, a1.z); a1.w = fmaf(b1, f.w, a1.w);
            a2.x = fmaf(b2, f.x, a2.x); a2.y = fmaf(b2, f.y, a2.y);
            a2.z = fmaf(b2, f.z, a2.z); a2.w = fmaf(b2, f.w, a2.w);
        }

        // --- combine even-k (half 0) and odd-k (half 1) partials: 15 SHFLs ---
        a0.x += __shfl_xor_sync(FULLM, a0.x, 16); a0.y += __shfl_xor_sync(FULLM, a0.y, 16);
        a0.z += __shfl_xor_sync(FULLM, a0.z, 16); a0.w += __shfl_xor_sync(FULLM, a0.w, 16);
        a1.x += __shfl_xor_sync(FULLM, a1.x, 16); a1.y += __shfl_xor_sync(FULLM, a1.y, 16);
        a1.z += __shfl_xor_sync(FULLM, a1.z, 16); a1.w += __shfl_xor_sync(FULLM, a1.w, 16);
        a2.x += __shfl_xor_sync(FULLM, a2.x, 16); a2.y += __shfl_xor_sync(FULLM, a2.y, 16);
        a2.z += __shfl_xor_sync(FULLM, a2.z, 16); a2.w += __shfl_xor_sync(FULLM, a2.w, 16);
        s0   += __shfl_xor_sync(FULLM, s0,   16);
        s1   += __shfl_xor_sync(FULLM, s1,   16);
        s2   += __shfl_xor_sync(FULLM, s2,   16);

        // --- write (V, 3*F): half 0 -> bins 0,2; half 1 -> bin 1 ---
        float* obase = out + (size_t)v * OUT_F + 4 * t;
        if (half == 0) {
            const float r0 = 1.0f / (s0 + EPSV);
            const float r2 = 1.0f / (s2 + EPSV);
            *reinterpret_cast<float4*>(obase) =
                make_float4(a0.x * r0, a0.y * r0, a0.z * r0, a0.w * r0);
            *reinterpret_cast<float4*>(obase + 2 * F_DIM) =
                make_float4(a2.x * r2, a2.y * r2, a2.z * r2, a2.w * r2);
        } else {
            const float r1 = 1.0f / (s1 + EPSV);
            *reinterpret_cast<float4*>(obase + F_DIM) =
                make_float4(a1.x * r1, a1.y * r1, a1.z * r1, a1.w * r1);
        }
    }
}

extern "C" void kernel_launch(void* const* d_in, const int* in_sizes, int n_in,
                              void* d_out, int out_size)
{
    const float* features = (const float*)d_in[0];
    const float* distsq   = (const float*)d_in[1];
    const int*   nidx     = (const int*)  d_in[2];
    const float* ls       = (const float*)d_in[3];
    float*       out      = (float*)d_out;

    int V = out_size / OUT_F;
    if (V <= 0) V = in_sizes[1] / K_NEIGH;

    const int threads = 32 * WARPS_PER_BLOCK;   // 8 warps/block, 8 vertices/block
    int blocks = (V * 32 + threads - 1) / threads;
    if (blocks < 1) blocks = 1;
    softpixel_kernel<<<blocks, threads>>>(features, distsq, nidx, ls, out, V);
}